// round 3
// baseline (speedup 1.0000x reference)
#include <cuda_runtime.h>
#include <math.h>

// ---------------- problem dims ----------------
#define Bc   2
#define Sc   4096
#define Dc   1024
#define Hc   16
#define NBc  64
#define NB2c 32
#define Rc   4
#define DFFc 4096
#define DHc  64
#define Cc   64
#define NCHc 64
#define BHS  (Bc*Hc*Sc)          // 131072
#define BSD  ((size_t)Bc*Sc*Dc)  // 8388608

// ---------------- workspace (static device memory; no allocations) ----------------
__device__ float g_ln[BSD];
__device__ float g_qk[BSD];
__device__ float g_v[BSD];
__device__ float g_attn[BSD];
__device__ float g_ffh[(size_t)Bc*Sc*DFFc];
__device__ float g_oall[(size_t)Rc*BHS*DHc];
__device__ float g_lall[(size_t)Rc*BHS];
__device__ int   g_buckets[(size_t)Rc*BHS];
__device__ int   g_order[(size_t)Rc*BHS];

// ---------------- packed f32x2 helpers (Blackwell FFMA2 path) ----------------
__device__ __forceinline__ unsigned long long f32x2_pack(float lo, float hi) {
    unsigned long long r;
    asm("mov.b64 %0, {%1, %2};" : "=l"(r) : "f"(lo), "f"(hi));
    return r;
}
__device__ __forceinline__ unsigned long long f32x2_fma(unsigned long long a,
                                                        unsigned long long b,
                                                        unsigned long long c) {
    unsigned long long d;
    asm("fma.rn.f32x2 %0, %1, %2, %3;" : "=l"(d) : "l"(a), "l"(b), "l"(c));
    return d;
}
__device__ __forceinline__ void f32x2_unpack(unsigned long long v, float& lo, float& hi) {
    asm("mov.b64 {%0, %1}, %2;" : "=f"(lo), "=f"(hi) : "l"(v));
}

// ---------------- layernorm: one block per row of D=1024 ----------------
__global__ void ln_kernel(const float* __restrict__ x, const float* __restrict__ g,
                          const float* __restrict__ bb, float* __restrict__ y)
{
    const int row = blockIdx.x;
    const float* xr = x + (size_t)row * Dc;
    float s1 = 0.f, s2 = 0.f;
    for (int i = threadIdx.x; i < Dc; i += 256) {
        float v = xr[i];
        s1 += v;
        s2 = fmaf(v, v, s2);
    }
    __shared__ float sh1[8], sh2[8];
    int lane = threadIdx.x & 31, w = threadIdx.x >> 5;
    #pragma unroll
    for (int o = 16; o > 0; o >>= 1) {
        s1 += __shfl_xor_sync(~0u, s1, o);
        s2 += __shfl_xor_sync(~0u, s2, o);
    }
    if (lane == 0) { sh1[w] = s1; sh2[w] = s2; }
    __syncthreads();
    if (w == 0) {
        s1 = (lane < 8) ? sh1[lane] : 0.f;
        s2 = (lane < 8) ? sh2[lane] : 0.f;
        #pragma unroll
        for (int o = 4; o > 0; o >>= 1) {
            s1 += __shfl_xor_sync(~0u, s1, o);
            s2 += __shfl_xor_sync(~0u, s2, o);
        }
        if (lane == 0) { sh1[0] = s1; sh2[0] = s2; }
    }
    __syncthreads();
    const float mean = sh1[0] * (1.f / Dc);
    const float var  = sh2[0] * (1.f / Dc) - mean * mean;
    const float inv  = 1.f / sqrtf(var + 1e-5f);
    float* yr = y + (size_t)row * Dc;
    for (int i = threadIdx.x; i < Dc; i += 256)
        yr[i] = (xr[i] - mean) * inv * g[i] + bb[i];
}

// ---------------- SGEMM 128x128x8, 8x8 microtile via FFMA2 with duplicated-A smem ----------------
// C[M,N] = A[M,K] @ B[K,N]  (+ bias[n]) (+ add[m,n]) (relu?)
__global__ void __launch_bounds__(256, 2) sgemm_kernel(
    const float* __restrict__ A, const float* __restrict__ Bm,
    float* __restrict__ Cm,
    const float* __restrict__ bias, const float* __restrict__ add,
    int M, int N, int K, int relu)
{
    __shared__ float As[8][256];   // duplicated: As[k][2*r] == As[k][2*r+1] == A[row0+r, k0+k]
    __shared__ float Bs[8][128];
    const int tid  = threadIdx.x;
    const int row0 = blockIdx.y * 128;
    const int col0 = blockIdx.x * 128;
    const int tx = tid & 15;
    const int ty = tid >> 4;

    const int aRow = tid >> 1;
    const int aCol = (tid & 1) << 2;
    const int bRow = tid >> 5;
    const int bCol = (tid & 31) << 2;

    const float* Aptr = A + (size_t)(row0 + aRow) * K + aCol;
    const float* Bptr = Bm + (size_t)bRow * N + col0 + bCol;

    // packed accumulators: 8 rows x 4 col-pairs
    unsigned long long acc2[8][4];
    #pragma unroll
    for (int i = 0; i < 8; i++)
        #pragma unroll
        for (int j = 0; j < 4; j++) acc2[i][j] = 0ull;

    // prefetch first k-tile into registers
    float4 a4 = *(const float4*)(Aptr);
    float4 b4 = *(const float4*)(Bptr);

    for (int k0 = 0; k0 < K; k0 += 8) {
        // commit current tile to smem (A duplicated via packed 64-bit stores)
        *(unsigned long long*)(&As[aCol + 0][2 * aRow]) = f32x2_pack(a4.x, a4.x);
        *(unsigned long long*)(&As[aCol + 1][2 * aRow]) = f32x2_pack(a4.y, a4.y);
        *(unsigned long long*)(&As[aCol + 2][2 * aRow]) = f32x2_pack(a4.z, a4.z);
        *(unsigned long long*)(&As[aCol + 3][2 * aRow]) = f32x2_pack(a4.w, a4.w);
        *(float4*)(&Bs[bRow][bCol]) = b4;
        __syncthreads();

        // issue next tile's global loads early (hide L2/DRAM latency behind compute)
        if (k0 + 8 < K) {
            a4 = *(const float4*)(Aptr + k0 + 8);
            b4 = *(const float4*)(Bptr + (size_t)(k0 + 8) * N);
        }

        #pragma unroll
        for (int k = 0; k < 8; k++) {
            // A pairs: rows ty*4 .. ty*4+3 and 64+ty*4 .. 64+ty*4+3, pre-duplicated
            ulonglong2 al0 = *(const ulonglong2*)(&As[k][ty * 8]);
            ulonglong2 al1 = *(const ulonglong2*)(&As[k][ty * 8 + 4]);
            ulonglong2 ah0 = *(const ulonglong2*)(&As[k][128 + ty * 8]);
            ulonglong2 ah1 = *(const ulonglong2*)(&As[k][128 + ty * 8 + 4]);
            // B pairs
            ulonglong2 bl = *(const ulonglong2*)(&Bs[k][tx * 4]);
            ulonglong2 bh = *(const ulonglong2*)(&Bs[k][64 + tx * 4]);
            unsigned long long ad[8] = {al0.x, al0.y, al1.x, al1.y,
                                        ah0.x, ah0.y, ah1.x, ah1.y};
            unsigned long long b2[4] = {bl.x, bl.y, bh.x, bh.y};
            #pragma unroll
            for (int i = 0; i < 8; i++)
                #pragma unroll
                for (int j = 0; j < 4; j++)
                    acc2[i][j] = f32x2_fma(ad[i], b2[j], acc2[i][j]);
        }
        __syncthreads();
    }

    #pragma unroll
    for (int i = 0; i < 8; i++) {
        const int m = row0 + ((i < 4) ? (ty * 4 + i) : (64 + ty * 4 + i - 4));
        #pragma unroll
        for (int j = 0; j < 4; j++) {
            const int n = col0 + ((j < 2) ? (tx * 4 + j * 2) : (64 + tx * 4 + (j - 2) * 2));
            float lo, hi;
            f32x2_unpack(acc2[i][j], lo, hi);
            if (bias) { lo += __ldg(&bias[n]); hi += __ldg(&bias[n + 1]); }
            if (add)  { lo += __ldg(&add[(size_t)m * N + n]); hi += __ldg(&add[(size_t)m * N + n + 1]); }
            if (relu) { lo = fmaxf(lo, 0.f); hi = fmaxf(hi, 0.f); }
            float2 o2 = make_float2(lo, hi);
            *(float2*)(&Cm[(size_t)m * N + n]) = o2;
        }
    }
}

// ---------------- LSH bucket assignment ----------------
__global__ void bucket_kernel(const float* __restrict__ qk, const float* __restrict__ rot,
                              int* __restrict__ buckets)
{
    __shared__ float srot[DHc * Rc * NB2c];  // 8192 floats
    for (int i = threadIdx.x; i < DHc * Rc * NB2c; i += blockDim.x) srot[i] = rot[i];
    __syncthreads();
    const int t = blockIdx.x * blockDim.x + threadIdx.x;
    if (t >= BHS) return;
    const int s = t & (Sc - 1);
    const int h = (t >> 12) & (Hc - 1);
    const int b = t >> 16;
    float q[DHc];
    const float* qr = qk + ((size_t)(b * Sc + s)) * Dc + h * DHc;
    #pragma unroll
    for (int d = 0; d < DHc; d++) q[d] = qr[d];
    #pragma unroll 1
    for (int r = 0; r < Rc; r++) {
        float vals[NB2c];
        #pragma unroll 1
        for (int k = 0; k < NB2c; k++) {
            float s0 = 0, s1 = 0, s2 = 0, s3 = 0;
            const int base = r * NB2c + k;
            #pragma unroll
            for (int d = 0; d < DHc; d += 4) {
                s0 = fmaf(q[d + 0], srot[(d + 0) * (Rc * NB2c) + base], s0);
                s1 = fmaf(q[d + 1], srot[(d + 1) * (Rc * NB2c) + base], s1);
                s2 = fmaf(q[d + 2], srot[(d + 2) * (Rc * NB2c) + base], s2);
                s3 = fmaf(q[d + 3], srot[(d + 3) * (Rc * NB2c) + base], s3);
            }
            vals[k] = (s0 + s1) + (s2 + s3);
        }
        float best = -1e30f; int bi = 0;
        #pragma unroll
        for (int k = 0; k < NB2c; k++) if (vals[k]  > best) { best = vals[k];  bi = k; }
        #pragma unroll
        for (int k = 0; k < NB2c; k++) if (-vals[k] > best) { best = -vals[k]; bi = NB2c + k; }
        buckets[(size_t)r * BHS + t] = bi;
    }
}

// ---------------- stable counting sort per (r,b,h) ----------------
__global__ void sort_kernel(const int* __restrict__ buckets, int* __restrict__ order)
{
    __shared__ int sb[Sc];       // 16KB
    __shared__ int cnt[NBc];
    __shared__ int off[NBc];
    const size_t base = (size_t)blockIdx.x * Sc;
    const int tid = threadIdx.x;
    if (tid < NBc) cnt[tid] = 0;
    __syncthreads();
    for (int i = tid; i < Sc; i += blockDim.x) {
        int bk = buckets[base + i];
        sb[i] = bk;
        atomicAdd(&cnt[bk], 1);
    }
    __syncthreads();
    if (tid == 0) {
        int a = 0;
        for (int k = 0; k < NBc; k++) { off[k] = a; a += cnt[k]; }
    }
    __syncthreads();
    if (tid < NBc) {
        int o = off[tid];
        for (int i = 0; i < Sc; i++)
            if (sb[i] == tid) order[base + (o++)] = i;
    }
}

// ---------------- chunked LSH attention, one block per (r,b,h,chunk) ----------------
__global__ void __launch_bounds__(64) attn_kernel(
    const float* __restrict__ qk, const float* __restrict__ v,
    const int* __restrict__ order, const int* __restrict__ buckets,
    float* __restrict__ oall, float* __restrict__ lall)
{
    extern __shared__ float smem[];
    float* Ke = smem;                 // 128*64
    float* Ve = smem + 128 * DHc;     // 128*64
    int*   be = (int*)(smem + 2 * 128 * DHc);
    int*   pe = be + 128;

    const int blk = blockIdx.x;
    const int n = blk & (NCHc - 1);
    const int h = (blk >> 6) & (Hc - 1);
    const int b = (blk >> 10) & (Bc - 1);
    const int r = blk >> 11;
    const int prev = (n + NCHc - 1) & (NCHc - 1);
    const size_t rbh = (((size_t)r * Bc + b) * Hc + h) * Sc;
    const int tid = threadIdx.x;

    for (int j = tid; j < 2 * Cc; j += 64) {
        const int spos = (j < Cc) ? (n * Cc + j) : (prev * Cc + (j - Cc));
        const int pk = order[rbh + spos];
        const float* kr = qk + ((size_t)(b * Sc + pk)) * Dc + h * DHc;
        const float* vr = v  + ((size_t)(b * Sc + pk)) * Dc + h * DHc;
        float ss = 0.f;
        float tmp[DHc];
        #pragma unroll
        for (int d = 0; d < DHc; d++) { float x = kr[d]; tmp[d] = x; ss = fmaf(x, x, ss); }
        const float sc = 1.f / (sqrtf(ss) + 1e-6f);
        #pragma unroll
        for (int d = 0; d < DHc; d++) { Ke[j * DHc + d] = tmp[d] * sc; Ve[j * DHc + d] = vr[d]; }
        be[j] = buckets[rbh + pk];
        pe[j] = pk;
    }
    __syncthreads();

    const int p  = pe[tid];
    const int bq = be[tid];
    float q[DHc];
    {
        const float* qr = qk + ((size_t)(b * Sc + p)) * Dc + h * DHc;
        #pragma unroll
        for (int d = 0; d < DHc; d++) q[d] = qr[d];
    }

    float mmax = -1e30f;
    for (int j = 0; j < 2 * Cc; j++) {
        const float4* k4 = (const float4*)(Ke + j * DHc);
        float s0 = 0, s1 = 0, s2 = 0, s3 = 0;
        #pragma unroll
        for (int t4 = 0; t4 < 16; t4++) {
            float4 kk = k4[t4];
            s0 = fmaf(q[4 * t4 + 0], kk.x, s0);
            s1 = fmaf(q[4 * t4 + 1], kk.y, s1);
            s2 = fmaf(q[4 * t4 + 2], kk.z, s2);
            s3 = fmaf(q[4 * t4 + 3], kk.w, s3);
        }
        float s = ((s0 + s1) + (s2 + s3)) * 0.125f;
        if (bq != be[j]) s = -1e9f;
        if (p == pe[j])  s = -1e5f;
        mmax = fmaxf(mmax, s);
    }

    float acc[DHc];
    #pragma unroll
    for (int d = 0; d < DHc; d++) acc[d] = 0.f;
    float sum = 0.f;
    for (int j = 0; j < 2 * Cc; j++) {
        const float4* k4 = (const float4*)(Ke + j * DHc);
        float s0 = 0, s1 = 0, s2 = 0, s3 = 0;
        #pragma unroll
        for (int t4 = 0; t4 < 16; t4++) {
            float4 kk = k4[t4];
            s0 = fmaf(q[4 * t4 + 0], kk.x, s0);
            s1 = fmaf(q[4 * t4 + 1], kk.y, s1);
            s2 = fmaf(q[4 * t4 + 2], kk.z, s2);
            s3 = fmaf(q[4 * t4 + 3], kk.w, s3);
        }
        float s = ((s0 + s1) + (s2 + s3)) * 0.125f;
        if (bq != be[j]) s = -1e9f;
        if (p == pe[j])  s = -1e5f;
        const float e = expf(s - mmax);
        sum += e;
        const float4* v4 = (const float4*)(Ve + j * DHc);
        #pragma unroll
        for (int t4 = 0; t4 < 16; t4++) {
            float4 vv = v4[t4];
            acc[4 * t4 + 0] = fmaf(e, vv.x, acc[4 * t4 + 0]);
            acc[4 * t4 + 1] = fmaf(e, vv.y, acc[4 * t4 + 1]);
            acc[4 * t4 + 2] = fmaf(e, vv.z, acc[4 * t4 + 2]);
            acc[4 * t4 + 3] = fmaf(e, vv.w, acc[4 * t4 + 3]);
        }
    }
    const float linv = 1.f / sum;
    float* orow = oall + (rbh + p) * DHc;
    #pragma unroll
    for (int d = 0; d < DHc; d++) orow[d] = acc[d] * linv;
    lall[rbh + p] = mmax + logf(sum);
}

// ---------------- combine rounds with softmax(logsumexp) weights ----------------
__global__ void combine_kernel(const float* __restrict__ oall, const float* __restrict__ lall,
                               float* __restrict__ out)
{
    const int t = blockIdx.x * blockDim.x + threadIdx.x;
    if (t >= BHS) return;
    const int s = t & (Sc - 1);
    const int h = (t >> 12) & (Hc - 1);
    const int b = t >> 16;
    const size_t idx = (size_t)t;
    const float l0 = lall[idx], l1 = lall[idx + BHS], l2 = lall[idx + 2 * (size_t)BHS], l3 = lall[idx + 3 * (size_t)BHS];
    const float m = fmaxf(fmaxf(l0, l1), fmaxf(l2, l3));
    float w0 = expf(l0 - m), w1 = expf(l1 - m), w2 = expf(l2 - m), w3 = expf(l3 - m);
    const float inv = 1.f / (w0 + w1 + w2 + w3);
    w0 *= inv; w1 *= inv; w2 *= inv; w3 *= inv;
    const float* o0 = oall + idx * DHc;
    const float* o1 = oall + (idx + BHS) * DHc;
    const float* o2 = oall + (idx + 2 * (size_t)BHS) * DHc;
    const float* o3 = oall + (idx + 3 * (size_t)BHS) * DHc;
    float* dst = out + ((size_t)(b * Sc + s)) * Dc + h * DHc;
    #pragma unroll
    for (int d = 0; d < DHc; d++)
        dst[d] = w0 * o0[d] + w1 * o1[d] + w2 * o2[d] + w3 * o3[d];
}

// ---------------- launch ----------------
extern "C" void kernel_launch(void* const* d_in, const int* in_sizes, int n_in,
                              void* d_out, int out_size)
{
    const float* x1    = (const float*)d_in[0];
    const float* x2    = (const float*)d_in[1];
    const float* Wqk   = (const float*)d_in[2];
    const float* Wv    = (const float*)d_in[3];
    const float* Wo    = (const float*)d_in[4];
    const float* ln1_g = (const float*)d_in[5];
    const float* ln1_b = (const float*)d_in[6];
    const float* W1    = (const float*)d_in[7];
    const float* bf1   = (const float*)d_in[8];
    const float* W2    = (const float*)d_in[9];
    const float* bf2   = (const float*)d_in[10];
    const float* ln2_g = (const float*)d_in[11];
    const float* ln2_b = (const float*)d_in[12];
    const float* rot   = (const float*)d_in[13];

    float *ln, *qk, *vv, *attn, *ffh, *oall, *lall;
    int *bk, *ord;
    cudaGetSymbolAddress((void**)&ln,   g_ln);
    cudaGetSymbolAddress((void**)&qk,   g_qk);
    cudaGetSymbolAddress((void**)&vv,   g_v);
    cudaGetSymbolAddress((void**)&attn, g_attn);
    cudaGetSymbolAddress((void**)&ffh,  g_ffh);
    cudaGetSymbolAddress((void**)&oall, g_oall);
    cudaGetSymbolAddress((void**)&lall, g_lall);
    cudaGetSymbolAddress((void**)&bk,   g_buckets);
    cudaGetSymbolAddress((void**)&ord,  g_order);

    float* y1 = (float*)d_out;
    float* y2 = y1 + BSD;

    const int ROWS = Bc * Sc;   // 8192

    ln_kernel<<<ROWS, 256>>>(x2, ln1_g, ln1_b, ln);

    dim3 gD(Dc / 128, ROWS / 128);
    sgemm_kernel<<<gD, 256>>>(ln, Wqk, qk, nullptr, nullptr, ROWS, Dc, Dc, 0);
    sgemm_kernel<<<gD, 256>>>(ln, Wv,  vv, nullptr, nullptr, ROWS, Dc, Dc, 0);

    bucket_kernel<<<BHS / 256, 256>>>(qk, rot, bk);
    sort_kernel<<<Rc * Bc * Hc, 256>>>(bk, ord);

    const int attn_smem = 2 * 128 * DHc * 4 + 2 * 128 * 4;  // 66560 B
    cudaFuncSetAttribute(attn_kernel, cudaFuncAttributeMaxDynamicSharedMemorySize, attn_smem);
    attn_kernel<<<Rc * Bc * Hc * NCHc, 64, attn_smem>>>(qk, vv, ord, bk, oall, lall);

    combine_kernel<<<BHS / 256, 256>>>(oall, lall, attn);

    sgemm_kernel<<<gD, 256>>>(attn, Wo, y1, nullptr, x1, ROWS, Dc, Dc, 0);

    ln_kernel<<<ROWS, 256>>>(y1, ln2_g, ln2_b, ln);

    dim3 gF(DFFc / 128, ROWS / 128);
    sgemm_kernel<<<gF, 256>>>(ln, W1, ffh, bf1, nullptr, ROWS, DFFc, Dc, 1);
    sgemm_kernel<<<gD, 256>>>(ffh, W2, y2, bf2, x2, ROWS, Dc, DFFc, 0);
}

// round 4
// speedup vs baseline: 1.6046x; 1.6046x over previous
#include <cuda_runtime.h>
#include <math.h>
#include <stdint.h>

// ---------------- problem dims ----------------
#define Bc   2
#define Sc   4096
#define Dc   1024
#define Hc   16
#define NBc  64
#define NB2c 32
#define Rc   4
#define DFFc 4096
#define DHc  64
#define Cc   64
#define NCHc 64
#define BHS  (Bc*Hc*Sc)          // 131072
#define BSD  ((size_t)Bc*Sc*Dc)  // 8388608

// ---------------- workspace (static device memory; no allocations) ----------------
__device__ float g_ln[BSD];
__device__ float g_qk[BSD];
__device__ float g_v[BSD];
__device__ float g_attn[BSD];
__device__ float g_ffh[(size_t)Bc*Sc*DFFc];
__device__ float g_oall[(size_t)Rc*BHS*DHc];
__device__ float g_lall[(size_t)Rc*BHS];
__device__ int   g_buckets[(size_t)Rc*BHS];
__device__ int   g_order[(size_t)Rc*BHS];

// ---------------- packed f32x2 helpers (Blackwell FFMA2 path) ----------------
__device__ __forceinline__ unsigned long long f32x2_pack(float lo, float hi) {
    unsigned long long r;
    asm("mov.b64 %0, {%1, %2};" : "=l"(r) : "f"(lo), "f"(hi));
    return r;
}
__device__ __forceinline__ unsigned long long f32x2_fma(unsigned long long a,
                                                        unsigned long long b,
                                                        unsigned long long c) {
    unsigned long long d;
    asm("fma.rn.f32x2 %0, %1, %2, %3;" : "=l"(d) : "l"(a), "l"(b), "l"(c));
    return d;
}
__device__ __forceinline__ void f32x2_unpack(unsigned long long v, float& lo, float& hi) {
    asm("mov.b64 {%0, %1}, %2;" : "=f"(lo), "=f"(hi) : "l"(v));
}

// ---------------- tf32 helpers ----------------
__device__ __forceinline__ uint32_t f2tf32(float f) {
    uint32_t r;
    asm("cvt.rna.tf32.f32 %0, %1;" : "=r"(r) : "f"(f));
    return r;
}
__device__ __forceinline__ void mma_tf32(float c[4],
                                         uint32_t a0, uint32_t a1, uint32_t a2, uint32_t a3,
                                         uint32_t b0, uint32_t b1) {
    asm volatile(
        "mma.sync.aligned.m16n8k8.row.col.f32.tf32.tf32.f32 "
        "{%0,%1,%2,%3}, {%4,%5,%6,%7}, {%8,%9}, {%0,%1,%2,%3};"
        : "+f"(c[0]), "+f"(c[1]), "+f"(c[2]), "+f"(c[3])
        : "r"(a0), "r"(a1), "r"(a2), "r"(a3), "r"(b0), "r"(b1));
}

// ---------------- layernorm: one block per row of D=1024 ----------------
__global__ void ln_kernel(const float* __restrict__ x, const float* __restrict__ g,
                          const float* __restrict__ bb, float* __restrict__ y)
{
    const int row = blockIdx.x;
    const float* xr = x + (size_t)row * Dc;
    float s1 = 0.f, s2 = 0.f;
    for (int i = threadIdx.x; i < Dc; i += 256) {
        float v = xr[i];
        s1 += v;
        s2 = fmaf(v, v, s2);
    }
    __shared__ float sh1[8], sh2[8];
    int lane = threadIdx.x & 31, w = threadIdx.x >> 5;
    #pragma unroll
    for (int o = 16; o > 0; o >>= 1) {
        s1 += __shfl_xor_sync(~0u, s1, o);
        s2 += __shfl_xor_sync(~0u, s2, o);
    }
    if (lane == 0) { sh1[w] = s1; sh2[w] = s2; }
    __syncthreads();
    if (w == 0) {
        s1 = (lane < 8) ? sh1[lane] : 0.f;
        s2 = (lane < 8) ? sh2[lane] : 0.f;
        #pragma unroll
        for (int o = 4; o > 0; o >>= 1) {
            s1 += __shfl_xor_sync(~0u, s1, o);
            s2 += __shfl_xor_sync(~0u, s2, o);
        }
        if (lane == 0) { sh1[0] = s1; sh2[0] = s2; }
    }
    __syncthreads();
    const float mean = sh1[0] * (1.f / Dc);
    const float var  = sh2[0] * (1.f / Dc) - mean * mean;
    const float inv  = 1.f / sqrtf(var + 1e-5f);
    float* yr = y + (size_t)row * Dc;
    for (int i = threadIdx.x; i < Dc; i += 256)
        yr[i] = (xr[i] - mean) * inv * g[i] + bb[i];
}

// ---------------- exact fp32 SGEMM (R2 version) for qk/v projections ----------------
__global__ void __launch_bounds__(256, 2) sgemm_kernel(
    const float* __restrict__ A, const float* __restrict__ Bm,
    float* __restrict__ Cm,
    const float* __restrict__ bias, const float* __restrict__ add,
    int M, int N, int K, int relu)
{
    __shared__ float As[8][128];
    __shared__ float Bs[8][128];
    const int tid  = threadIdx.x;
    const int row0 = blockIdx.y * 128;
    const int col0 = blockIdx.x * 128;
    const int tx = tid & 15;
    const int ty = tid >> 4;

    const int aRow = tid >> 1;
    const int aCol = (tid & 1) << 2;
    const int bRow = tid >> 5;
    const int bCol = (tid & 31) << 2;

    const float* Aptr = A + (size_t)(row0 + aRow) * K + aCol;
    const float* Bptr = Bm + (size_t)bRow * N + col0 + bCol;

    unsigned long long acc2[8][4];
    #pragma unroll
    for (int i = 0; i < 8; i++)
        #pragma unroll
        for (int j = 0; j < 4; j++) acc2[i][j] = 0ull;

    float4 a4 = *(const float4*)(Aptr);
    float4 b4 = *(const float4*)(Bptr);

    for (int k0 = 0; k0 < K; k0 += 8) {
        As[aCol + 0][aRow] = a4.x;
        As[aCol + 1][aRow] = a4.y;
        As[aCol + 2][aRow] = a4.z;
        As[aCol + 3][aRow] = a4.w;
        *(float4*)(&Bs[bRow][bCol]) = b4;
        __syncthreads();

        if (k0 + 8 < K) {
            a4 = *(const float4*)(Aptr + k0 + 8);
            b4 = *(const float4*)(Bptr + (size_t)(k0 + 8) * N);
        }

        #pragma unroll
        for (int k = 0; k < 8; k++) {
            float4 a0 = *(const float4*)(&As[k][ty * 4]);
            float4 a1 = *(const float4*)(&As[k][64 + ty * 4]);
            unsigned long long b2[4];
            const unsigned long long* bp0 = (const unsigned long long*)(&Bs[k][tx * 4]);
            b2[0] = bp0[0];
            b2[1] = bp0[1];
            const unsigned long long* bp1 = (const unsigned long long*)(&Bs[k][64 + tx * 4]);
            b2[2] = bp1[0];
            b2[3] = bp1[1];
            float av[8] = {a0.x, a0.y, a0.z, a0.w, a1.x, a1.y, a1.z, a1.w};
            #pragma unroll
            for (int i = 0; i < 8; i++) {
                const unsigned long long ad = f32x2_pack(av[i], av[i]);
                #pragma unroll
                for (int j = 0; j < 4; j++)
                    acc2[i][j] = f32x2_fma(ad, b2[j], acc2[i][j]);
            }
        }
        __syncthreads();
    }

    #pragma unroll
    for (int i = 0; i < 8; i++) {
        const int m = row0 + ((i < 4) ? (ty * 4 + i) : (64 + ty * 4 + i - 4));
        #pragma unroll
        for (int j = 0; j < 4; j++) {
            const int n = col0 + ((j < 2) ? (tx * 4 + j * 2) : (64 + tx * 4 + (j - 2) * 2));
            float lo, hi;
            f32x2_unpack(acc2[i][j], lo, hi);
            if (bias) { lo += __ldg(&bias[n]); hi += __ldg(&bias[n + 1]); }
            if (add)  { lo += __ldg(&add[(size_t)m * N + n]); hi += __ldg(&add[(size_t)m * N + n + 1]); }
            if (relu) { lo = fmaxf(lo, 0.f); hi = fmaxf(hi, 0.f); }
            float2 o2 = make_float2(lo, hi);
            *(float2*)(&Cm[(size_t)m * N + n]) = o2;
        }
    }
}

// ---------------- tf32 tensor-core GEMM (Wo / W1 / W2) ----------------
// 128x128 block, 8 warps (2x4), warp tile 64x32, k-tile 32, m16n8k8 mma.
__global__ void __launch_bounds__(256) tf32gemm_kernel(
    const float* __restrict__ A, const float* __restrict__ Bm,
    float* __restrict__ Cm,
    const float* __restrict__ bias, const float* __restrict__ add,
    int M, int N, int K, int relu)
{
    __shared__ float As[128][36];   // padded: bank-conflict-free fragment loads
    __shared__ float Bs[32][132];

    const int tid  = threadIdx.x;
    const int lane = tid & 31;
    const int warp = tid >> 5;
    const int wm = warp >> 2;            // 0..1
    const int wn = warp & 3;             // 0..3
    const int row0 = blockIdx.y * 128;
    const int col0 = blockIdx.x * 128;

    const int arow = tid >> 3;            // 0..31 (+32*i)
    const int acol = (tid & 7) << 2;      // 0..28
    const int brow = tid >> 5;            // 0..7  (+8*i)
    const int bcol = (tid & 31) << 2;     // 0..124

    float acc[4][4][4];
    #pragma unroll
    for (int mi = 0; mi < 4; mi++)
        #pragma unroll
        for (int ni = 0; ni < 4; ni++)
            #pragma unroll
            for (int c = 0; c < 4; c++) acc[mi][ni][c] = 0.f;

    const float* Abase = A + (size_t)(row0 + arow) * K + acol;
    const float* Bbase = Bm + (size_t)brow * N + col0 + bcol;

    float4 aF[4], bF[4];
    #pragma unroll
    for (int i = 0; i < 4; i++) aF[i] = *(const float4*)(Abase + (size_t)(32 * i) * K);
    #pragma unroll
    for (int i = 0; i < 4; i++) bF[i] = *(const float4*)(Bbase + (size_t)(8 * i) * N);

    for (int k0 = 0; k0 < K; k0 += 32) {
        // stage (with tf32 rounding)
        #pragma unroll
        for (int i = 0; i < 4; i++) {
            float* d = &As[arow + 32 * i][acol];
            d[0] = __uint_as_float(f2tf32(aF[i].x));
            d[1] = __uint_as_float(f2tf32(aF[i].y));
            d[2] = __uint_as_float(f2tf32(aF[i].z));
            d[3] = __uint_as_float(f2tf32(aF[i].w));
        }
        #pragma unroll
        for (int i = 0; i < 4; i++) {
            float* d = &Bs[brow + 8 * i][bcol];
            d[0] = __uint_as_float(f2tf32(bF[i].x));
            d[1] = __uint_as_float(f2tf32(bF[i].y));
            d[2] = __uint_as_float(f2tf32(bF[i].z));
            d[3] = __uint_as_float(f2tf32(bF[i].w));
        }
        __syncthreads();

        if (k0 + 32 < K) {
            #pragma unroll
            for (int i = 0; i < 4; i++)
                aF[i] = *(const float4*)(Abase + (size_t)(32 * i) * K + k0 + 32);
            #pragma unroll
            for (int i = 0; i < 4; i++)
                bF[i] = *(const float4*)(Bbase + (size_t)(8 * i + k0 + 32) * N);
        }

        #pragma unroll
        for (int ks = 0; ks < 4; ks++) {
            const int kb = ks * 8;
            uint32_t af[4][4];
            #pragma unroll
            for (int mi = 0; mi < 4; mi++) {
                const int r = wm * 64 + mi * 16 + (lane >> 2);
                const int c = kb + (lane & 3);
                af[mi][0] = __float_as_uint(As[r][c]);
                af[mi][1] = __float_as_uint(As[r + 8][c]);
                af[mi][2] = __float_as_uint(As[r][c + 4]);
                af[mi][3] = __float_as_uint(As[r + 8][c + 4]);
            }
            uint32_t bf[4][2];
            #pragma unroll
            for (int ni = 0; ni < 4; ni++) {
                const int c = wn * 32 + ni * 8 + (lane >> 2);
                bf[ni][0] = __float_as_uint(Bs[kb + (lane & 3)][c]);
                bf[ni][1] = __float_as_uint(Bs[kb + (lane & 3) + 4][c]);
            }
            #pragma unroll
            for (int mi = 0; mi < 4; mi++)
                #pragma unroll
                for (int ni = 0; ni < 4; ni++)
                    mma_tf32(acc[mi][ni], af[mi][0], af[mi][1], af[mi][2], af[mi][3],
                             bf[ni][0], bf[ni][1]);
        }
        __syncthreads();
    }

    // epilogue
    #pragma unroll
    for (int mi = 0; mi < 4; mi++) {
        #pragma unroll
        for (int ni = 0; ni < 4; ni++) {
            const int m = row0 + wm * 64 + mi * 16 + (lane >> 2);
            const int n = col0 + wn * 32 + ni * 8 + (lane & 3) * 2;
            float c0 = acc[mi][ni][0], c1 = acc[mi][ni][1];
            float c2 = acc[mi][ni][2], c3 = acc[mi][ni][3];
            if (bias) {
                const float b0 = __ldg(&bias[n]), b1 = __ldg(&bias[n + 1]);
                c0 += b0; c1 += b1; c2 += b0; c3 += b1;
            }
            if (add) {
                c0 += __ldg(&add[(size_t)m * N + n]);
                c1 += __ldg(&add[(size_t)m * N + n + 1]);
                c2 += __ldg(&add[(size_t)(m + 8) * N + n]);
                c3 += __ldg(&add[(size_t)(m + 8) * N + n + 1]);
            }
            if (relu) {
                c0 = fmaxf(c0, 0.f); c1 = fmaxf(c1, 0.f);
                c2 = fmaxf(c2, 0.f); c3 = fmaxf(c3, 0.f);
            }
            *(float2*)(&Cm[(size_t)m * N + n]) = make_float2(c0, c1);
            *(float2*)(&Cm[(size_t)(m + 8) * N + n]) = make_float2(c2, c3);
        }
    }
}

// ---------------- LSH bucket assignment ----------------
__global__ void bucket_kernel(const float* __restrict__ qk, const float* __restrict__ rot,
                              int* __restrict__ buckets)
{
    __shared__ float srot[DHc * Rc * NB2c];  // 8192 floats
    for (int i = threadIdx.x; i < DHc * Rc * NB2c; i += blockDim.x) srot[i] = rot[i];
    __syncthreads();
    const int t = blockIdx.x * blockDim.x + threadIdx.x;
    if (t >= BHS) return;
    const int s = t & (Sc - 1);
    const int h = (t >> 12) & (Hc - 1);
    const int b = t >> 16;
    float q[DHc];
    const float* qr = qk + ((size_t)(b * Sc + s)) * Dc + h * DHc;
    #pragma unroll
    for (int d = 0; d < DHc; d++) q[d] = qr[d];
    #pragma unroll 1
    for (int r = 0; r < Rc; r++) {
        float vals[NB2c];
        #pragma unroll 1
        for (int k = 0; k < NB2c; k++) {
            float s0 = 0, s1 = 0, s2 = 0, s3 = 0;
            const int base = r * NB2c + k;
            #pragma unroll
            for (int d = 0; d < DHc; d += 4) {
                s0 = fmaf(q[d + 0], srot[(d + 0) * (Rc * NB2c) + base], s0);
                s1 = fmaf(q[d + 1], srot[(d + 1) * (Rc * NB2c) + base], s1);
                s2 = fmaf(q[d + 2], srot[(d + 2) * (Rc * NB2c) + base], s2);
                s3 = fmaf(q[d + 3], srot[(d + 3) * (Rc * NB2c) + base], s3);
            }
            vals[k] = (s0 + s1) + (s2 + s3);
        }
        float best = -1e30f; int bi = 0;
        #pragma unroll
        for (int k = 0; k < NB2c; k++) if (vals[k]  > best) { best = vals[k];  bi = k; }
        #pragma unroll
        for (int k = 0; k < NB2c; k++) if (-vals[k] > best) { best = -vals[k]; bi = NB2c + k; }
        buckets[(size_t)r * BHS + t] = bi;
    }
}

// ---------------- stable counting sort per (r,b,h) ----------------
__global__ void sort_kernel(const int* __restrict__ buckets, int* __restrict__ order)
{
    __shared__ int sb[Sc];       // 16KB
    __shared__ int cnt[NBc];
    __shared__ int off[NBc];
    const size_t base = (size_t)blockIdx.x * Sc;
    const int tid = threadIdx.x;
    if (tid < NBc) cnt[tid] = 0;
    __syncthreads();
    for (int i = tid; i < Sc; i += blockDim.x) {
        int bk = buckets[base + i];
        sb[i] = bk;
        atomicAdd(&cnt[bk], 1);
    }
    __syncthreads();
    if (tid == 0) {
        int a = 0;
        for (int k = 0; k < NBc; k++) { off[k] = a; a += cnt[k]; }
    }
    __syncthreads();
    if (tid < NBc) {
        int o = off[tid];
        for (int i = 0; i < Sc; i++)
            if (sb[i] == tid) order[base + (o++)] = i;
    }
}

// ---------------- chunked LSH attention, one block per (r,b,h,chunk) ----------------
__global__ void __launch_bounds__(64) attn_kernel(
    const float* __restrict__ qk, const float* __restrict__ v,
    const int* __restrict__ order, const int* __restrict__ buckets,
    float* __restrict__ oall, float* __restrict__ lall)
{
    extern __shared__ float smem[];
    float* Ke = smem;                 // 128*64
    float* Ve = smem + 128 * DHc;     // 128*64
    int*   be = (int*)(smem + 2 * 128 * DHc);
    int*   pe = be + 128;

    const int blk = blockIdx.x;
    const int n = blk & (NCHc - 1);
    const int h = (blk >> 6) & (Hc - 1);
    const int b = (blk >> 10) & (Bc - 1);
    const int r = blk >> 11;
    const int prev = (n + NCHc - 1) & (NCHc - 1);
    const size_t rbh = (((size_t)r * Bc + b) * Hc + h) * Sc;
    const int tid = threadIdx.x;

    for (int j = tid; j < 2 * Cc; j += 64) {
        const int spos = (j < Cc) ? (n * Cc + j) : (prev * Cc + (j - Cc));
        const int pk = order[rbh + spos];
        const float* kr = qk + ((size_t)(b * Sc + pk)) * Dc + h * DHc;
        const float* vr = v  + ((size_t)(b * Sc + pk)) * Dc + h * DHc;
        float ss = 0.f;
        float tmp[DHc];
        #pragma unroll
        for (int d = 0; d < DHc; d++) { float x = kr[d]; tmp[d] = x; ss = fmaf(x, x, ss); }
        const float sc = 1.f / (sqrtf(ss) + 1e-6f);
        #pragma unroll
        for (int d = 0; d < DHc; d++) { Ke[j * DHc + d] = tmp[d] * sc; Ve[j * DHc + d] = vr[d]; }
        be[j] = buckets[rbh + pk];
        pe[j] = pk;
    }
    __syncthreads();

    const int p  = pe[tid];
    const int bq = be[tid];
    float q[DHc];
    {
        const float* qr = qk + ((size_t)(b * Sc + p)) * Dc + h * DHc;
        #pragma unroll
        for (int d = 0; d < DHc; d++) q[d] = qr[d];
    }

    float mmax = -1e30f;
    for (int j = 0; j < 2 * Cc; j++) {
        const float4* k4 = (const float4*)(Ke + j * DHc);
        float s0 = 0, s1 = 0, s2 = 0, s3 = 0;
        #pragma unroll
        for (int t4 = 0; t4 < 16; t4++) {
            float4 kk = k4[t4];
            s0 = fmaf(q[4 * t4 + 0], kk.x, s0);
            s1 = fmaf(q[4 * t4 + 1], kk.y, s1);
            s2 = fmaf(q[4 * t4 + 2], kk.z, s2);
            s3 = fmaf(q[4 * t4 + 3], kk.w, s3);
        }
        float s = ((s0 + s1) + (s2 + s3)) * 0.125f;
        if (bq != be[j]) s = -1e9f;
        if (p == pe[j])  s = -1e5f;
        mmax = fmaxf(mmax, s);
    }

    float acc[DHc];
    #pragma unroll
    for (int d = 0; d < DHc; d++) acc[d] = 0.f;
    float sum = 0.f;
    for (int j = 0; j < 2 * Cc; j++) {
        const float4* k4 = (const float4*)(Ke + j * DHc);
        float s0 = 0, s1 = 0, s2 = 0, s3 = 0;
        #pragma unroll
        for (int t4 = 0; t4 < 16; t4++) {
            float4 kk = k4[t4];
            s0 = fmaf(q[4 * t4 + 0], kk.x, s0);
            s1 = fmaf(q[4 * t4 + 1], kk.y, s1);
            s2 = fmaf(q[4 * t4 + 2], kk.z, s2);
            s3 = fmaf(q[4 * t4 + 3], kk.w, s3);
        }
        float s = ((s0 + s1) + (s2 + s3)) * 0.125f;
        if (bq != be[j]) s = -1e9f;
        if (p == pe[j])  s = -1e5f;
        const float e = expf(s - mmax);
        sum += e;
        const float4* v4 = (const float4*)(Ve + j * DHc);
        #pragma unroll
        for (int t4 = 0; t4 < 16; t4++) {
            float4 vv = v4[t4];
            acc[4 * t4 + 0] = fmaf(e, vv.x, acc[4 * t4 + 0]);
            acc[4 * t4 + 1] = fmaf(e, vv.y, acc[4 * t4 + 1]);
            acc[4 * t4 + 2] = fmaf(e, vv.z, acc[4 * t4 + 2]);
            acc[4 * t4 + 3] = fmaf(e, vv.w, acc[4 * t4 + 3]);
        }
    }
    const float linv = 1.f / sum;
    float* orow = oall + (rbh + p) * DHc;
    #pragma unroll
    for (int d = 0; d < DHc; d++) orow[d] = acc[d] * linv;
    lall[rbh + p] = mmax + logf(sum);
}

// ---------------- combine rounds with softmax(logsumexp) weights ----------------
__global__ void combine_kernel(const float* __restrict__ oall, const float* __restrict__ lall,
                               float* __restrict__ out)
{
    const int t = blockIdx.x * blockDim.x + threadIdx.x;
    if (t >= BHS) return;
    const int s = t & (Sc - 1);
    const int h = (t >> 12) & (Hc - 1);
    const int b = t >> 16;
    const size_t idx = (size_t)t;
    const float l0 = lall[idx], l1 = lall[idx + BHS], l2 = lall[idx + 2 * (size_t)BHS], l3 = lall[idx + 3 * (size_t)BHS];
    const float m = fmaxf(fmaxf(l0, l1), fmaxf(l2, l3));
    float w0 = expf(l0 - m), w1 = expf(l1 - m), w2 = expf(l2 - m), w3 = expf(l3 - m);
    const float inv = 1.f / (w0 + w1 + w2 + w3);
    w0 *= inv; w1 *= inv; w2 *= inv; w3 *= inv;
    const float* o0 = oall + idx * DHc;
    const float* o1 = oall + (idx + BHS) * DHc;
    const float* o2 = oall + (idx + 2 * (size_t)BHS) * DHc;
    const float* o3 = oall + (idx + 3 * (size_t)BHS) * DHc;
    float* dst = out + ((size_t)(b * Sc + s)) * Dc + h * DHc;
    #pragma unroll
    for (int d = 0; d < DHc; d++)
        dst[d] = w0 * o0[d] + w1 * o1[d] + w2 * o2[d] + w3 * o3[d];
}

// ---------------- launch ----------------
extern "C" void kernel_launch(void* const* d_in, const int* in_sizes, int n_in,
                              void* d_out, int out_size)
{
    const float* x1    = (const float*)d_in[0];
    const float* x2    = (const float*)d_in[1];
    const float* Wqk   = (const float*)d_in[2];
    const float* Wv    = (const float*)d_in[3];
    const float* Wo    = (const float*)d_in[4];
    const float* ln1_g = (const float*)d_in[5];
    const float* ln1_b = (const float*)d_in[6];
    const float* W1    = (const float*)d_in[7];
    const float* bf1   = (const float*)d_in[8];
    const float* W2    = (const float*)d_in[9];
    const float* bf2   = (const float*)d_in[10];
    const float* ln2_g = (const float*)d_in[11];
    const float* ln2_b = (const float*)d_in[12];
    const float* rot   = (const float*)d_in[13];

    float *ln, *qk, *vv, *attn, *ffh, *oall, *lall;
    int *bk, *ord;
    cudaGetSymbolAddress((void**)&ln,   g_ln);
    cudaGetSymbolAddress((void**)&qk,   g_qk);
    cudaGetSymbolAddress((void**)&vv,   g_v);
    cudaGetSymbolAddress((void**)&attn, g_attn);
    cudaGetSymbolAddress((void**)&ffh,  g_ffh);
    cudaGetSymbolAddress((void**)&oall, g_oall);
    cudaGetSymbolAddress((void**)&lall, g_lall);
    cudaGetSymbolAddress((void**)&bk,   g_buckets);
    cudaGetSymbolAddress((void**)&ord,  g_order);

    float* y1 = (float*)d_out;
    float* y2 = y1 + BSD;

    const int ROWS = Bc * Sc;   // 8192

    ln_kernel<<<ROWS, 256>>>(x2, ln1_g, ln1_b, ln);

    // exact fp32 path for qk/v (feeds buckets + attention)
    dim3 gD(Dc / 128, ROWS / 128);
    sgemm_kernel<<<gD, 256>>>(ln, Wqk, qk, nullptr, nullptr, ROWS, Dc, Dc, 0);
    sgemm_kernel<<<gD, 256>>>(ln, Wv,  vv, nullptr, nullptr, ROWS, Dc, Dc, 0);

    bucket_kernel<<<BHS / 256, 256>>>(qk, rot, bk);
    sort_kernel<<<Rc * Bc * Hc, 256>>>(bk, ord);

    const int attn_smem = 2 * 128 * DHc * 4 + 2 * 128 * 4;  // 66560 B
    cudaFuncSetAttribute(attn_kernel, cudaFuncAttributeMaxDynamicSharedMemorySize, attn_smem);
    attn_kernel<<<Rc * Bc * Hc * NCHc, 64, attn_smem>>>(qk, vv, ord, bk, oall, lall);

    combine_kernel<<<BHS / 256, 256>>>(oall, lall, attn);

    // tf32 tensor-core path for Wo / W1 / W2 (residual-diluted outputs)
    tf32gemm_kernel<<<gD, 256>>>(attn, Wo, y1, nullptr, x1, ROWS, Dc, Dc, 0);

    ln_kernel<<<ROWS, 256>>>(y1, ln2_g, ln2_b, ln);

    dim3 gF(DFFc / 128, ROWS / 128);
    tf32gemm_kernel<<<gF, 256>>>(ln, W1, ffh, bf1, nullptr, ROWS, DFFc, Dc, 1);
    tf32gemm_kernel<<<gD, 256>>>(ffh, W2, y2, bf2, x2, ROWS, Dc, DFFc, 0);
}